// round 8
// baseline (speedup 1.0000x reference)
#include <cuda_runtime.h>
#include <cuda_fp16.h>
#include <cstdint>

// ---------------------------------------------------------------------------
// Problem constants
// ---------------------------------------------------------------------------
#define BSZ     4
#define QLEN    1024
#define DEMB    768
#define DMODEL  1024
#define NHEAD   16
#define DHEAD   64
#define M_ROWS  (QLEN*BSZ)          // 4096, row r = q*4 + b
#define H3      (3*NHEAD*DHEAD)     // 3072
#define SCALE   (0.125f)

// ---------------------------------------------------------------------------
// Scratch (fp16 everywhere)
// ---------------------------------------------------------------------------
__device__ __align__(16) __half g_we_h[BSZ*QLEN*DEMB];
__device__ __align__(16) __half g_embw_h[DEMB*DMODEL];
__device__ __align__(16) __half g_w0_h[DMODEL*H3];
__device__ __align__(16) __half g_w1_h[DMODEL*H3];
__device__ __align__(16) __half g_h_h[M_ROWS*DMODEL];
__device__ __align__(16) __half g_heads_h[M_ROWS*H3];
__device__ __align__(16) __half g_P_h[64u*1024u*1024u];    // 128 MB [bn][i][j]

// ---------------------------------------------------------------------------
// Helpers
// ---------------------------------------------------------------------------
__device__ __forceinline__ void cpa16(void* dst, const void* src) {
    uint32_t d = (uint32_t)__cvta_generic_to_shared(dst);
    asm volatile("cp.async.cg.shared.global [%0], [%1], 16;" :: "r"(d), "l"(src));
}
__device__ __forceinline__ void cpcommit() {
    asm volatile("cp.async.commit_group;");
}
template<int NN> __device__ __forceinline__ void cpwait() {
    asm volatile("cp.async.wait_group %0;" :: "n"(NN));
}

__device__ __forceinline__ void ldm_x4(uint32_t r[4], const void* p) {
    uint32_t a = (uint32_t)__cvta_generic_to_shared(p);
    asm volatile("ldmatrix.sync.aligned.m8n8.x4.shared.b16 {%0,%1,%2,%3}, [%4];"
                 : "=r"(r[0]), "=r"(r[1]), "=r"(r[2]), "=r"(r[3]) : "r"(a));
}
__device__ __forceinline__ void ldm_x4t(uint32_t r[4], const void* p) {
    uint32_t a = (uint32_t)__cvta_generic_to_shared(p);
    asm volatile("ldmatrix.sync.aligned.m8n8.x4.trans.shared.b16 {%0,%1,%2,%3}, [%4];"
                 : "=r"(r[0]), "=r"(r[1]), "=r"(r[2]), "=r"(r[3]) : "r"(a));
}

__device__ __forceinline__ void mma_f16(float c[4], const uint32_t a[4],
                                        uint32_t b0, uint32_t b1) {
    asm volatile(
        "mma.sync.aligned.m16n8k16.row.col.f32.f16.f16.f32 "
        "{%0,%1,%2,%3}, {%4,%5,%6,%7}, {%8,%9}, {%0,%1,%2,%3};"
        : "+f"(c[0]), "+f"(c[1]), "+f"(c[2]), "+f"(c[3])
        : "r"(a[0]), "r"(a[1]), "r"(a[2]), "r"(a[3]), "r"(b0), "r"(b1));
}

// ---------------------------------------------------------------------------
// fp32 -> fp16 convert
// ---------------------------------------------------------------------------
__global__ __launch_bounds__(256)
void f32_to_f16(const float4* __restrict__ in, uint2* __restrict__ out, int n4)
{
    int i = blockIdx.x * blockDim.x + threadIdx.x;
    if (i < n4) {
        float4 v = in[i];
        __half2 lo = __floats2half2_rn(v.x, v.y);
        __half2 hi = __floats2half2_rn(v.z, v.w);
        out[i] = make_uint2(*(uint32_t*)&lo, *(uint32_t*)&hi);
    }
}

// ---------------------------------------------------------------------------
// FP16 GEMM: BM=128 BN=128 BK=32, 256 threads, 4-stage cp.async ring.
// ---------------------------------------------------------------------------
#define GA_LD 40
#define GB_LD 136
#define GA_SZ (128*GA_LD)   // 5120
#define GB_SZ (32*GB_LD)    // 4352
#define GSTAGES 4
#define GEMM_SMEM_BYTES (GSTAGES*(GA_SZ+GB_SZ)*2)   // 75776

template<int AMODE, int K, int N, bool BIAS>
__global__ __launch_bounds__(256, 2)
void gemm_h(const __half* __restrict__ A, const __half* __restrict__ B,
            const float* __restrict__ bias, __half* __restrict__ C)
{
    extern __shared__ __half smp[];
    __half* As = smp;
    __half* Bs = smp + GSTAGES * GA_SZ;

    const int t    = threadIdx.x;
    const int lane = t & 31;
    const int w    = t >> 5;
    const int wm   = w >> 2;
    const int wn   = w & 3;
    const int mblk = blockIdx.y;
    const int nblk = blockIdx.x;
    const int KT   = K / 32;

    float acc[4][4][4];
    #pragma unroll
    for (int im = 0; im < 4; im++)
        #pragma unroll
        for (int g = 0; g < 4; g++)
            #pragma unroll
            for (int j = 0; j < 4; j++) acc[im][g][j] = 0.f;

    auto issue = [&](int kt) {
        __half* Ab = As + (kt % GSTAGES) * GA_SZ;
        __half* Bb = Bs + (kt % GSTAGES) * GB_SZ;
        #pragma unroll
        for (int it = 0; it < 2; it++) {
            int ca = t + it * 256;
            int m = ca >> 2, c = ca & 3;
            int mg = mblk * 128 + m;
            const __half* src;
            if (AMODE == 0)
                src = A + (long)((mg & 3) * QLEN + (mg >> 2)) * K + kt * 32 + c * 8;
            else
                src = A + (long)mg * K + kt * 32 + c * 8;
            cpa16(Ab + m * GA_LD + c * 8, src);
        }
        #pragma unroll
        for (int it = 0; it < 2; it++) {
            int cb = t + it * 256;
            int k = cb >> 4, c = cb & 15;
            cpa16(Bb + k * GB_LD + c * 8,
                  B + (long)(kt * 32 + k) * N + nblk * 128 + c * 8);
        }
        cpcommit();
    };

    issue(0);
    issue(1);
    issue(2);

    for (int kt = 0; kt < KT; kt++) {
        if (kt < KT - 2)      cpwait<2>();
        else if (kt == KT - 2) cpwait<1>();
        else                   cpwait<0>();
        __syncthreads();
        if (kt + 3 < KT) issue(kt + 3);

        const __half* Ab = As + (kt % GSTAGES) * GA_SZ;
        const __half* Bb = Bs + (kt % GSTAGES) * GB_SZ;

        #pragma unroll
        for (int ks = 0; ks < 2; ks++) {
            uint32_t af[4][4];
            #pragma unroll
            for (int im = 0; im < 4; im++)
                ldm_x4(af[im], Ab + (wm * 64 + im * 16 + (lane & 15)) * GA_LD +
                               ks * 16 + (lane >> 4) * 8);
            uint32_t bf[2][4];
            #pragma unroll
            for (int ib = 0; ib < 2; ib++)
                ldm_x4t(bf[ib], Bb + (ks * 16 + (lane & 15)) * GB_LD +
                                wn * 32 + ib * 16 + (lane >> 4) * 8);
            #pragma unroll
            for (int im = 0; im < 4; im++) {
                mma_f16(acc[im][0], af[im], bf[0][0], bf[0][1]);
                mma_f16(acc[im][1], af[im], bf[0][2], bf[0][3]);
                mma_f16(acc[im][2], af[im], bf[1][0], bf[1][1]);
                mma_f16(acc[im][3], af[im], bf[1][2], bf[1][3]);
            }
        }
    }

    #pragma unroll
    for (int im = 0; im < 4; im++) {
        #pragma unroll
        for (int g = 0; g < 4; g++) {
            int r0 = mblk * 128 + wm * 64 + im * 16 + (lane >> 2);
            int c0 = nblk * 128 + wn * 32 + g * 8 + 2 * (lane & 3);
            float b0v = 0.f, b1v = 0.f;
            if (BIAS) { b0v = bias[c0]; b1v = bias[c0 + 1]; }
            __half2 v0 = __floats2half2_rn(acc[im][g][0] + b0v, acc[im][g][1] + b1v);
            __half2 v1 = __floats2half2_rn(acc[im][g][2] + b0v, acc[im][g][3] + b1v);
            *(__half2*)&C[(long)r0 * N + c0]       = v0;
            *(__half2*)&C[(long)(r0 + 8) * N + c0] = v1;
        }
    }
}

// ---------------------------------------------------------------------------
// Fused attention. CTA = (bn, 64-row q tile), 512 threads (16 warps),
// warp tile 16x16. S [64][1024] fp16 smem; exact softmax; P fp16 in place.
// ---------------------------------------------------------------------------
#define SP_LD 1032
#define AQ_LD 72
#define KV_SZ (64*AQ_LD)
#define ATTN_SMEM_BYTES ((64*SP_LD + 64*AQ_LD + 3*KV_SZ) * 2)   // 168960

template<bool LAST>
__global__ __launch_bounds__(512, 1)
void attn_h(const __half* __restrict__ heads, __half* __restrict__ outh,
            float* __restrict__ outf, __half* __restrict__ Pout)
{
    extern __shared__ __half sm[];
    __half* S  = sm;                       // [64][1032]
    __half* Q  = sm + 64 * SP_LD;          // [64][72]
    __half* KV = Q + 64 * AQ_LD;           // 3 x [64][72]

    const int t    = threadIdx.x;
    const int lane = t & 31;
    const int w    = t >> 5;   // 0..15
    const int wm   = w >> 2;   // 0..3 (16 rows)
    const int wn   = w & 3;    // 0..3 (16 cols)
    const int bn   = blockIdx.x;
    const int qt   = blockIdx.y;
    const int b    = bn >> 4;
    const int n    = bn & 15;

    auto issueKV = [&](int u) {
        int which = (u < 16) ? 1 : 2;
        int jt = u & 15;
        __half* dst = KV + (u % 3) * KV_SZ;
        int jj = t >> 3, c = t & 7;          // 512 threads: one chunk each
        cpa16(dst + jj * AQ_LD + c * 8,
              heads + (long)((jt * 64 + jj) * 4 + b) * H3 +
              which * DMODEL + n * 64 + c * 8);
        cpcommit();
    };

    // prologue: Q + K0, then K1
    {
        int ir = t >> 3, c = t & 7;
        cpa16(Q + ir * AQ_LD + c * 8,
              heads + (long)((qt * 64 + ir) * 4 + b) * H3 + n * 64 + c * 8);
    }
    issueKV(0);
    issueKV(1);

    float oacc[2][4];
    #pragma unroll
    for (int g = 0; g < 2; g++)
        #pragma unroll
        for (int j = 0; j < 4; j++) oacc[g][j] = 0.f;

    for (int u = 0; u < 32; u++) {
        if (u < 31) cpwait<1>(); else cpwait<0>();
        __syncthreads();
        if (u + 2 < 32) issueKV(u + 2);

        if (u == 16) {
            // ---- softmax: 16 warps x 4 rows ----
            for (int rr = 0; rr < 4; rr++) {
                const int r = w * 4 + rr;
                float v[32];
                float mx = -1e30f;
                #pragma unroll
                for (int c = 0; c < 16; c++) {
                    __half2 h2 = *(__half2*)&S[r * SP_LD + c * 64 + lane * 2];
                    float2 f = __half22float2(h2);
                    v[2 * c] = f.x; v[2 * c + 1] = f.y;
                    mx = fmaxf(mx, fmaxf(f.x, f.y));
                }
                #pragma unroll
                for (int o = 16; o; o >>= 1)
                    mx = fmaxf(mx, __shfl_xor_sync(0xffffffffu, mx, o));
                float s = 0.f;
                #pragma unroll
                for (int c = 0; c < 32; c++) { v[c] = __expf(v[c] - mx); s += v[c]; }
                #pragma unroll
                for (int o = 16; o; o >>= 1) s += __shfl_xor_sync(0xffffffffu, s, o);
                const float inv = 1.f / s;
                const int gi = qt * 64 + r;
                #pragma unroll
                for (int c = 0; c < 16; c++) {
                    __half2 p = __floats2half2_rn(v[2 * c] * inv, v[2 * c + 1] * inv);
                    *(__half2*)&S[r * SP_LD + c * 64 + lane * 2] = p;
                    if (LAST)
                        *(__half2*)&Pout[(size_t)bn * 1048576 +
                                         (size_t)gi * 1024 + c * 64 + lane * 2] = p;
                }
            }
            __syncthreads();
        }

        const __half* Kb = KV + (u % 3) * KV_SZ;

        if (u < 16) {
            // ---- S[64 x 64-jtile] = Q K^T ----
            const int jt = u;
            float sacc[2][4];
            #pragma unroll
            for (int g = 0; g < 2; g++)
                #pragma unroll
                for (int j = 0; j < 4; j++) sacc[g][j] = 0.f;
            #pragma unroll
            for (int ks = 0; ks < 4; ks++) {
                uint32_t aq[4];
                ldm_x4(aq, Q + (wm * 16 + (lane & 15)) * AQ_LD +
                           ks * 16 + (lane >> 4) * 8);
                uint32_t bk[4];
                ldm_x4(bk, Kb + (wn * 16 + (lane & 15)) * AQ_LD +
                           ks * 16 + (lane >> 4) * 8);
                mma_f16(sacc[0], aq, bk[0], bk[2]);
                mma_f16(sacc[1], aq, bk[1], bk[3]);
            }
            #pragma unroll
            for (int g = 0; g < 2; g++) {
                int r = wm * 16 + (lane >> 2);
                int c = jt * 64 + wn * 16 + g * 8 + 2 * (lane & 3);
                *(__half2*)&S[r * SP_LD + c] =
                    __floats2half2_rn(sacc[g][0] * SCALE, sacc[g][1] * SCALE);
                *(__half2*)&S[(r + 8) * SP_LD + c] =
                    __floats2half2_rn(sacc[g][2] * SCALE, sacc[g][3] * SCALE);
            }
        } else {
            // ---- O += P[:, jtile] V[jtile] ----
            const int jt = u - 16;
            #pragma unroll
            for (int ks = 0; ks < 4; ks++) {
                uint32_t ap[4];
                ldm_x4(ap, S + (wm * 16 + (lane & 15)) * SP_LD +
                           jt * 64 + ks * 16 + (lane >> 4) * 8);
                uint32_t bv[4];
                ldm_x4t(bv, Kb + (ks * 16 + (lane & 15)) * AQ_LD +
                            wn * 16 + (lane >> 4) * 8);
                mma_f16(oacc[0], ap, bv[0], bv[1]);
                mma_f16(oacc[1], ap, bv[2], bv[3]);
            }
        }
    }

    // ---- epilogue ----
    #pragma unroll
    for (int g = 0; g < 2; g++) {
        int r = wm * 16 + (lane >> 2);
        int c = n * 64 + wn * 16 + g * 8 + 2 * (lane & 3);
        long gr0 = (long)((qt * 64 + r) * 4 + b);
        long gr1 = gr0 + 32;   // (r+8)*4
        if (LAST) {
            *(float2*)&outf[gr0 * DMODEL + c] = make_float2(oacc[g][0], oacc[g][1]);
            *(float2*)&outf[gr1 * DMODEL + c] = make_float2(oacc[g][2], oacc[g][3]);
        } else {
            *(__half2*)&outh[gr0 * DMODEL + c] = __floats2half2_rn(oacc[g][0], oacc[g][1]);
            *(__half2*)&outh[gr1 * DMODEL + c] = __floats2half2_rn(oacc[g][2], oacc[g][3]);
        }
    }
}

// ---------------------------------------------------------------------------
// P scratch fp16 [bn][i][j] -> out fp32 [i][j][b][n]
// ---------------------------------------------------------------------------
__global__ __launch_bounds__(256)
void transpose_P(const __half* __restrict__ P, float* __restrict__ out)
{
    __shared__ float T[64][65];
    const int jc = blockIdx.x;
    const int i  = blockIdx.y;
    const int t  = threadIdx.x;

    #pragma unroll
    for (int it = 0; it < 2; it++) {
        int idx = t + it * 256;
        int bnv = idx >> 3, c = idx & 7;
        uint4 raw = *(const uint4*)(P + (size_t)bnv * 1048576 +
                                    (size_t)i * 1024 + jc * 64 + c * 8);
        const __half2* hp = (const __half2*)&raw;
        #pragma unroll
        for (int e = 0; e < 4; e++) {
            float2 f = __half22float2(hp[e]);
            T[c * 8 + 2 * e][bnv]     = f.x;
            T[c * 8 + 2 * e + 1][bnv] = f.y;
        }
    }
    __syncthreads();
    #pragma unroll
    for (int it = 0; it < 4; it++) {
        int idx = t + it * 256;
        int jv = idx >> 4, b4 = idx & 15;
        float4 v = make_float4(T[jv][b4 * 4], T[jv][b4 * 4 + 1],
                               T[jv][b4 * 4 + 2], T[jv][b4 * 4 + 3]);
        *(float4*)(out + (size_t)i * 65536 + (size_t)(jc * 64 + jv) * 64 + b4 * 4) = v;
    }
}

// ---------------------------------------------------------------------------
// Launch
// ---------------------------------------------------------------------------
extern "C" void kernel_launch(void* const* d_in, const int* in_sizes, int n_in,
                              void* d_out, int out_size)
{
    const float* word_emb = (const float*)d_in[0];
    const float* emb_w    = (const float*)d_in[1];
    const float* emb_b    = (const float*)d_in[2];
    const float* qkv_w0   = (const float*)d_in[3];
    const float* qkv_w1   = (const float*)d_in[4];

    float* core_out = (float*)d_out;
    float* attn_out = (float*)d_out + (size_t)M_ROWS * DMODEL;

    __half *we_h, *embw_h, *w0_h, *w1_h, *h_h, *heads_h, *P_h;
    cudaGetSymbolAddress((void**)&we_h,    g_we_h);
    cudaGetSymbolAddress((void**)&embw_h,  g_embw_h);
    cudaGetSymbolAddress((void**)&w0_h,    g_w0_h);
    cudaGetSymbolAddress((void**)&w1_h,    g_w1_h);
    cudaGetSymbolAddress((void**)&h_h,     g_h_h);
    cudaGetSymbolAddress((void**)&heads_h, g_heads_h);
    cudaGetSymbolAddress((void**)&P_h,     g_P_h);

    static bool attr_done = false;
    if (!attr_done) {
        cudaFuncSetAttribute(gemm_h<0, DEMB, DMODEL, true>,
            cudaFuncAttributeMaxDynamicSharedMemorySize, GEMM_SMEM_BYTES);
        cudaFuncSetAttribute(gemm_h<1, DMODEL, H3, false>,
            cudaFuncAttributeMaxDynamicSharedMemorySize, GEMM_SMEM_BYTES);
        cudaFuncSetAttribute(attn_h<false>,
            cudaFuncAttributeMaxDynamicSharedMemorySize, ATTN_SMEM_BYTES);
        cudaFuncSetAttribute(attn_h<true>,
            cudaFuncAttributeMaxDynamicSharedMemorySize, ATTN_SMEM_BYTES);
        attr_done = true;
    }

    // 0) convert inputs to fp16
    f32_to_f16<<<(BSZ*QLEN*DEMB/4 + 255)/256, 256>>>(
        (const float4*)word_emb, (uint2*)we_h, BSZ*QLEN*DEMB/4);
    f32_to_f16<<<(DEMB*DMODEL/4 + 255)/256, 256>>>(
        (const float4*)emb_w, (uint2*)embw_h, DEMB*DMODEL/4);
    f32_to_f16<<<(DMODEL*H3/4 + 255)/256, 256>>>(
        (const float4*)qkv_w0, (uint2*)w0_h, DMODEL*H3/4);
    f32_to_f16<<<(DMODEL*H3/4 + 255)/256, 256>>>(
        (const float4*)qkv_w1, (uint2*)w1_h, DMODEL*H3/4);

    // 1) h = transpose(word_emb) @ emb_w + emb_b
    gemm_h<0, DEMB, DMODEL, true><<<dim3(DMODEL/128, M_ROWS/128), 256,
        GEMM_SMEM_BYTES>>>(we_h, embw_h, emb_b, h_h);

    // 2) MHA #0
    gemm_h<1, DMODEL, H3, false><<<dim3(H3/128, M_ROWS/128), 256,
        GEMM_SMEM_BYTES>>>(h_h, w0_h, nullptr, heads_h);
    attn_h<false><<<dim3(64, 16), 512, ATTN_SMEM_BYTES>>>(
        heads_h, h_h, nullptr, nullptr);

    // 3) MHA #1 (keeps attn maps)
    gemm_h<1, DMODEL, H3, false><<<dim3(H3/128, M_ROWS/128), 256,
        GEMM_SMEM_BYTES>>>(h_h, w1_h, nullptr, heads_h);
    attn_h<true><<<dim3(64, 16), 512, ATTN_SMEM_BYTES>>>(
        heads_h, nullptr, core_out, P_h);

    // 4) attn_prob reformat [bn][i][j] -> [i][j][b][n]
    transpose_P<<<dim3(16, 1024), 256>>>(P_h, attn_out);
}

// round 9
// speedup vs baseline: 1.0671x; 1.0671x over previous
#include <cuda_runtime.h>
#include <cuda_fp16.h>
#include <cstdint>

// ---------------------------------------------------------------------------
// Problem constants
// ---------------------------------------------------------------------------
#define BSZ     4
#define QLEN    1024
#define DEMB    768
#define DMODEL  1024
#define NHEAD   16
#define DHEAD   64
#define M_ROWS  (QLEN*BSZ)          // 4096, row r = q*4 + b
#define H3      (3*NHEAD*DHEAD)     // 3072
#define SCALE   (0.125f)

// ---------------------------------------------------------------------------
// Scratch (fp16 everywhere)
// ---------------------------------------------------------------------------
__device__ __align__(16) __half g_we_h[BSZ*QLEN*DEMB];
__device__ __align__(16) __half g_embw_h[DEMB*DMODEL];
__device__ __align__(16) __half g_w0_h[DMODEL*H3];
__device__ __align__(16) __half g_w1_h[DMODEL*H3];
__device__ __align__(16) __half g_h_h[M_ROWS*DMODEL];
__device__ __align__(16) __half g_heads_h[M_ROWS*H3];
__device__ __align__(16) __half g_P_h[64u*1024u*1024u];    // 128 MB [bn][i][j]

// ---------------------------------------------------------------------------
// Helpers
// ---------------------------------------------------------------------------
__device__ __forceinline__ void cpa16(void* dst, const void* src) {
    uint32_t d = (uint32_t)__cvta_generic_to_shared(dst);
    asm volatile("cp.async.cg.shared.global [%0], [%1], 16;" :: "r"(d), "l"(src));
}
__device__ __forceinline__ void cpcommit() {
    asm volatile("cp.async.commit_group;");
}
template<int NN> __device__ __forceinline__ void cpwait() {
    asm volatile("cp.async.wait_group %0;" :: "n"(NN));
}

__device__ __forceinline__ void ldm_x4(uint32_t r[4], const void* p) {
    uint32_t a = (uint32_t)__cvta_generic_to_shared(p);
    asm volatile("ldmatrix.sync.aligned.m8n8.x4.shared.b16 {%0,%1,%2,%3}, [%4];"
                 : "=r"(r[0]), "=r"(r[1]), "=r"(r[2]), "=r"(r[3]) : "r"(a));
}
__device__ __forceinline__ void ldm_x4t(uint32_t r[4], const void* p) {
    uint32_t a = (uint32_t)__cvta_generic_to_shared(p);
    asm volatile("ldmatrix.sync.aligned.m8n8.x4.trans.shared.b16 {%0,%1,%2,%3}, [%4];"
                 : "=r"(r[0]), "=r"(r[1]), "=r"(r[2]), "=r"(r[3]) : "r"(a));
}

__device__ __forceinline__ void mma_f16(float c[4], const uint32_t a[4],
                                        uint32_t b0, uint32_t b1) {
    asm volatile(
        "mma.sync.aligned.m16n8k16.row.col.f32.f16.f16.f32 "
        "{%0,%1,%2,%3}, {%4,%5,%6,%7}, {%8,%9}, {%0,%1,%2,%3};"
        : "+f"(c[0]), "+f"(c[1]), "+f"(c[2]), "+f"(c[3])
        : "r"(a[0]), "r"(a[1]), "r"(a[2]), "r"(a[3]), "r"(b0), "r"(b1));
}

// ---------------------------------------------------------------------------
// fp32 -> fp16 convert, all four inputs in one launch (grid-stride segments)
// ---------------------------------------------------------------------------
#define N4_WE   (BSZ*QLEN*DEMB/4)     // 786432
#define N4_EW   (DEMB*DMODEL/4)       // 196608
#define N4_W    (DMODEL*H3/4)         // 786432
#define N4_TOT  (N4_WE + N4_EW + 2*N4_W)

__global__ __launch_bounds__(256)
void cvt_all(const float4* __restrict__ we, const float4* __restrict__ ew,
             const float4* __restrict__ w0, const float4* __restrict__ w1,
             uint2* __restrict__ owe, uint2* __restrict__ oew,
             uint2* __restrict__ ow0, uint2* __restrict__ ow1)
{
    int i = blockIdx.x * blockDim.x + threadIdx.x;
    if (i >= N4_TOT) return;
    const float4* src; uint2* dst; int j;
    if (i < N4_WE)                     { src = we; dst = owe; j = i; }
    else if (i < N4_WE + N4_EW)        { src = ew; dst = oew; j = i - N4_WE; }
    else if (i < N4_WE + N4_EW + N4_W) { src = w0; dst = ow0; j = i - N4_WE - N4_EW; }
    else                               { src = w1; dst = ow1; j = i - N4_WE - N4_EW - N4_W; }
    float4 v = src[j];
    __half2 lo = __floats2half2_rn(v.x, v.y);
    __half2 hi = __floats2half2_rn(v.z, v.w);
    dst[j] = make_uint2(*(uint32_t*)&lo, *(uint32_t*)&hi);
}

// ---------------------------------------------------------------------------
// FP16 GEMM: BM=128 BN=128 BK=32, 256 threads, 3-stage cp.async ring.
// ---------------------------------------------------------------------------
#define GA_LD 40
#define GB_LD 136
#define GA_SZ (128*GA_LD)   // 5120
#define GB_SZ (32*GB_LD)    // 4352
#define GEMM_SMEM_BYTES (3*(GA_SZ+GB_SZ)*2)   // 56832

template<int AMODE, int K, int N, bool BIAS>
__global__ __launch_bounds__(256, 2)
void gemm_h(const __half* __restrict__ A, const __half* __restrict__ B,
            const float* __restrict__ bias, __half* __restrict__ C)
{
    extern __shared__ __half smp[];
    __half* As = smp;
    __half* Bs = smp + 3 * GA_SZ;

    const int t    = threadIdx.x;
    const int lane = t & 31;
    const int w    = t >> 5;
    const int wm   = w >> 2;
    const int wn   = w & 3;
    const int mblk = blockIdx.y;
    const int nblk = blockIdx.x;
    const int KT   = K / 32;

    float acc[4][4][4];
    #pragma unroll
    for (int im = 0; im < 4; im++)
        #pragma unroll
        for (int g = 0; g < 4; g++)
            #pragma unroll
            for (int j = 0; j < 4; j++) acc[im][g][j] = 0.f;

    auto issue = [&](int kt) {
        __half* Ab = As + (kt % 3) * GA_SZ;
        __half* Bb = Bs + (kt % 3) * GB_SZ;
        #pragma unroll
        for (int it = 0; it < 2; it++) {
            int ca = t + it * 256;
            int m = ca >> 2, c = ca & 3;
            int mg = mblk * 128 + m;
            const __half* src;
            if (AMODE == 0)
                src = A + (long)((mg & 3) * QLEN + (mg >> 2)) * K + kt * 32 + c * 8;
            else
                src = A + (long)mg * K + kt * 32 + c * 8;
            cpa16(Ab + m * GA_LD + c * 8, src);
        }
        #pragma unroll
        for (int it = 0; it < 2; it++) {
            int cb = t + it * 256;
            int k = cb >> 4, c = cb & 15;
            cpa16(Bb + k * GB_LD + c * 8,
                  B + (long)(kt * 32 + k) * N + nblk * 128 + c * 8);
        }
        cpcommit();
    };

    issue(0);
    issue(1);

    for (int kt = 0; kt < KT; kt++) {
        if (kt < KT - 1) cpwait<1>(); else cpwait<0>();
        __syncthreads();
        if (kt + 2 < KT) issue(kt + 2);

        const __half* Ab = As + (kt % 3) * GA_SZ;
        const __half* Bb = Bs + (kt % 3) * GB_SZ;

        #pragma unroll
        for (int ks = 0; ks < 2; ks++) {
            uint32_t af[4][4];
            #pragma unroll
            for (int im = 0; im < 4; im++)
                ldm_x4(af[im], Ab + (wm * 64 + im * 16 + (lane & 15)) * GA_LD +
                               ks * 16 + (lane >> 4) * 8);
            uint32_t bf[2][4];
            #pragma unroll
            for (int ib = 0; ib < 2; ib++)
                ldm_x4t(bf[ib], Bb + (ks * 16 + (lane & 15)) * GB_LD +
                                wn * 32 + ib * 16 + (lane >> 4) * 8);
            #pragma unroll
            for (int im = 0; im < 4; im++) {
                mma_f16(acc[im][0], af[im], bf[0][0], bf[0][1]);
                mma_f16(acc[im][1], af[im], bf[0][2], bf[0][3]);
                mma_f16(acc[im][2], af[im], bf[1][0], bf[1][1]);
                mma_f16(acc[im][3], af[im], bf[1][2], bf[1][3]);
            }
        }
    }

    #pragma unroll
    for (int im = 0; im < 4; im++) {
        #pragma unroll
        for (int g = 0; g < 4; g++) {
            int r0 = mblk * 128 + wm * 64 + im * 16 + (lane >> 2);
            int c0 = nblk * 128 + wn * 32 + g * 8 + 2 * (lane & 3);
            float b0v = 0.f, b1v = 0.f;
            if (BIAS) { b0v = bias[c0]; b1v = bias[c0 + 1]; }
            __half2 v0 = __floats2half2_rn(acc[im][g][0] + b0v, acc[im][g][1] + b1v);
            __half2 v1 = __floats2half2_rn(acc[im][g][2] + b0v, acc[im][g][3] + b1v);
            *(__half2*)&C[(long)r0 * N + c0]       = v0;
            *(__half2*)&C[(long)(r0 + 8) * N + c0] = v1;
        }
    }
}

// ---------------------------------------------------------------------------
// Fused attention. CTA = (bn, 64-row q tile), 256 threads (8 warps),
// warp tile 16x32. S [64][1024] fp16 smem; exact softmax; P fp16 in place.
// Q fragments hoisted into registers (invariant across all 16 S j-tiles).
// ---------------------------------------------------------------------------
#define SP_LD 1032
#define AQ_LD 72
#define KV_SZ (64*AQ_LD)
#define ATTN_SMEM_BYTES ((64*SP_LD + 64*AQ_LD + 3*KV_SZ) * 2)   // 168960

template<bool LAST>
__global__ __launch_bounds__(256, 1)
void attn_h(const __half* __restrict__ heads, __half* __restrict__ outh,
            float* __restrict__ outf, __half* __restrict__ Pout)
{
    extern __shared__ __half sm[];
    __half* S  = sm;                       // [64][1032]
    __half* Q  = sm + 64 * SP_LD;          // [64][72]
    __half* KV = Q + 64 * AQ_LD;           // 3 x [64][72]

    const int t    = threadIdx.x;
    const int lane = t & 31;
    const int w    = t >> 5;
    const int wm   = w >> 1;   // 0..3 (16 rows each)
    const int wn   = w & 1;    // 0..1 (32 cols each)
    const int bn   = blockIdx.x;   // 0..63
    const int qt   = blockIdx.y;   // 0..15
    const int b    = bn >> 4;
    const int n    = bn & 15;

    auto issueKV = [&](int u) {
        int which = (u < 16) ? 1 : 2;
        int jt = u & 15;
        __half* dst = KV + (u % 3) * KV_SZ;
        #pragma unroll
        for (int it = 0; it < 2; it++) {
            int idx = t + it * 256;           // 0..511
            int jj = idx >> 3, c = idx & 7;
            cpa16(dst + jj * AQ_LD + c * 8,
                  heads + (long)((jt * 64 + jj) * 4 + b) * H3 +
                  which * DMODEL + n * 64 + c * 8);
        }
        cpcommit();
    };

    // prologue: Q + K0 (group 0), K1 (group 1)
    #pragma unroll
    for (int it = 0; it < 2; it++) {
        int idx = t + it * 256;
        int ir = idx >> 3, c = idx & 7;
        cpa16(Q + ir * AQ_LD + c * 8,
              heads + (long)((qt * 64 + ir) * 4 + b) * H3 + n * 64 + c * 8);
    }
    issueKV(0);
    issueKV(1);

    float oacc[4][4];
    #pragma unroll
    for (int g = 0; g < 4; g++)
        #pragma unroll
        for (int j = 0; j < 4; j++) oacc[g][j] = 0.f;

    uint32_t qf[4][4];   // hoisted Q fragments (per ks)

    for (int u = 0; u < 32; u++) {
        if (u < 31) cpwait<1>(); else cpwait<0>();
        __syncthreads();
        if (u + 2 < 32) issueKV(u + 2);

        if (u == 0) {
            // Q tile resident (group 0 complete): load fragments once
            #pragma unroll
            for (int ks = 0; ks < 4; ks++)
                ldm_x4(qf[ks], Q + (wm * 16 + (lane & 15)) * AQ_LD +
                               ks * 16 + (lane >> 4) * 8);
        }

        if (u == 16) {
            // ---- softmax (8 rows per warp), S complete ----
            for (int rr = 0; rr < 8; rr++) {
                const int r = w * 8 + rr;
                float v[32];
                float mx = -1e30f;
                #pragma unroll
                for (int c = 0; c < 16; c++) {
                    __half2 h2 = *(__half2*)&S[r * SP_LD + c * 64 + lane * 2];
                    float2 f = __half22float2(h2);
                    v[2 * c] = f.x; v[2 * c + 1] = f.y;
                    mx = fmaxf(mx, fmaxf(f.x, f.y));
                }
                #pragma unroll
                for (int o = 16; o; o >>= 1)
                    mx = fmaxf(mx, __shfl_xor_sync(0xffffffffu, mx, o));
                float s = 0.f;
                #pragma unroll
                for (int c = 0; c < 32; c++) { v[c] = __expf(v[c] - mx); s += v[c]; }
                #pragma unroll
                for (int o = 16; o; o >>= 1) s += __shfl_xor_sync(0xffffffffu, s, o);
                const float inv = 1.f / s;
                const int gi = qt * 64 + r;
                #pragma unroll
                for (int c = 0; c < 16; c++) {
                    __half2 p = __floats2half2_rn(v[2 * c] * inv, v[2 * c + 1] * inv);
                    *(__half2*)&S[r * SP_LD + c * 64 + lane * 2] = p;
                    if (LAST)
                        *(__half2*)&Pout[(size_t)bn * 1048576 +
                                         (size_t)gi * 1024 + c * 64 + lane * 2] = p;
                }
            }
            __syncthreads();
        }

        const __half* Kb = KV + (u % 3) * KV_SZ;

        if (u < 16) {
            // ---- S[64 x 64-jtile] = Q K^T ----
            const int jt = u;
            float sacc[4][4];
            #pragma unroll
            for (int g = 0; g < 4; g++)
                #pragma unroll
                for (int j = 0; j < 4; j++) sacc[g][j] = 0.f;
            #pragma unroll
            for (int ks = 0; ks < 4; ks++) {
                uint32_t bk0[4], bk1[4];
                ldm_x4(bk0, Kb + (wn * 32 + (lane & 15)) * AQ_LD +
                            ks * 16 + (lane >> 4) * 8);
                ldm_x4(bk1, Kb + (wn * 32 + 16 + (lane & 15)) * AQ_LD +
                            ks * 16 + (lane >> 4) * 8);
                mma_f16(sacc[0], qf[ks], bk0[0], bk0[2]);
                mma_f16(sacc[1], qf[ks], bk0[1], bk0[3]);
                mma_f16(sacc[2], qf[ks], bk1[0], bk1[2]);
                mma_f16(sacc[3], qf[ks], bk1[1], bk1[3]);
            }
            #pragma unroll
            for (int g = 0; g < 4; g++) {
                int r = wm * 16 + (lane >> 2);
                int c = jt * 64 + wn * 32 + g * 8 + 2 * (lane & 3);
                *(__half2*)&S[r * SP_LD + c] =
                    __floats2half2_rn(sacc[g][0] * SCALE, sacc[g][1] * SCALE);
                *(__half2*)&S[(r + 8) * SP_LD + c] =
                    __floats2half2_rn(sacc[g][2] * SCALE, sacc[g][3] * SCALE);
            }
        } else {
            // ---- O += P[:, jtile] V[jtile] ----
            const int jt = u - 16;
            #pragma unroll
            for (int ks = 0; ks < 4; ks++) {
                uint32_t ap[4];
                ldm_x4(ap, S + (wm * 16 + (lane & 15)) * SP_LD +
                           jt * 64 + ks * 16 + (lane >> 4) * 8);
                uint32_t bv0[4], bv1[4];
                ldm_x4t(bv0, Kb + (ks * 16 + (lane & 15)) * AQ_LD +
                             wn * 32 + (lane >> 4) * 8);
                ldm_x4t(bv1, Kb + (ks * 16 + (lane & 15)) * AQ_LD +
                             wn * 32 + 16 + (lane >> 4) * 8);
                mma_f16(oacc[0], ap, bv0[0], bv0[1]);
                mma_f16(oacc[1], ap, bv0[2], bv0[3]);
                mma_f16(oacc[2], ap, bv1[0], bv1[1]);
                mma_f16(oacc[3], ap, bv1[2], bv1[3]);
            }
        }
    }

    // ---- epilogue: out[(i*4+b)][n*64+d] ----
    #pragma unroll
    for (int g = 0; g < 4; g++) {
        int r = wm * 16 + (lane >> 2);
        int c = n * 64 + wn * 32 + g * 8 + 2 * (lane & 3);
        long gr0 = (long)((qt * 64 + r) * 4 + b);
        long gr1 = gr0 + 32;   // (r+8)*4
        if (LAST) {
            *(float2*)&outf[gr0 * DMODEL + c] = make_float2(oacc[g][0], oacc[g][1]);
            *(float2*)&outf[gr1 * DMODEL + c] = make_float2(oacc[g][2], oacc[g][3]);
        } else {
            *(__half2*)&outh[gr0 * DMODEL + c] = __floats2half2_rn(oacc[g][0], oacc[g][1]);
            *(__half2*)&outh[gr1 * DMODEL + c] = __floats2half2_rn(oacc[g][2], oacc[g][3]);
        }
    }
}

// ---------------------------------------------------------------------------
// P scratch fp16 [bn][i][j] -> out fp32 [i][j][b][n]
// ---------------------------------------------------------------------------
__global__ __launch_bounds__(256)
void transpose_P(const __half* __restrict__ P, float* __restrict__ out)
{
    __shared__ float T[64][65];
    const int jc = blockIdx.x;
    const int i  = blockIdx.y;
    const int t  = threadIdx.x;

    #pragma unroll
    for (int it = 0; it < 2; it++) {
        int idx = t + it * 256;
        int bnv = idx >> 3, c = idx & 7;
        uint4 raw = *(const uint4*)(P + (size_t)bnv * 1048576 +
                                    (size_t)i * 1024 + jc * 64 + c * 8);
        const __half2* hp = (const __half2*)&raw;
        #pragma unroll
        for (int e = 0; e < 4; e++) {
            float2 f = __half22float2(hp[e]);
            T[c * 8 + 2 * e][bnv]     = f.x;
            T[c * 8 + 2 * e + 1][bnv] = f.y;
        }
    }
    __syncthreads();
    #pragma unroll
    for (int it = 0; it < 4; it++) {
        int idx = t + it * 256;
        int jv = idx >> 4, b4 = idx & 15;
        float4 v = make_float4(T[jv][b4 * 4], T[jv][b4 * 4 + 1],
                               T[jv][b4 * 4 + 2], T[jv][b4 * 4 + 3]);
        *(float4*)(out + (size_t)i * 65536 + (size_t)(jc * 64 + jv) * 64 + b4 * 4) = v;
    }
}

// ---------------------------------------------------------------------------
// Launch
// ---------------------------------------------------------------------------
extern "C" void kernel_launch(void* const* d_in, const int* in_sizes, int n_in,
                              void* d_out, int out_size)
{
    const float* word_emb = (const float*)d_in[0];
    const float* emb_w    = (const float*)d_in[1];
    const float* emb_b    = (const float*)d_in[2];
    const float* qkv_w0   = (const float*)d_in[3];
    const float* qkv_w1   = (const float*)d_in[4];

    float* core_out = (float*)d_out;
    float* attn_out = (float*)d_out + (size_t)M_ROWS * DMODEL;

    __half *we_h, *embw_h, *w0_h, *w1_h, *h_h, *heads_h, *P_h;
    cudaGetSymbolAddress((void**)&we_h,    g_we_h);
    cudaGetSymbolAddress((void**)&embw_h,  g_embw_h);
    cudaGetSymbolAddress((void**)&w0_h,    g_w0_h);
    cudaGetSymbolAddress((void**)&w1_h,    g_w1_h);
    cudaGetSymbolAddress((void**)&h_h,     g_h_h);
    cudaGetSymbolAddress((void**)&heads_h, g_heads_h);
    cudaGetSymbolAddress((void**)&P_h,     g_P_h);

    static bool attr_done = false;
    if (!attr_done) {
        cudaFuncSetAttribute(gemm_h<0, DEMB, DMODEL, true>,
            cudaFuncAttributeMaxDynamicSharedMemorySize, GEMM_SMEM_BYTES);
        cudaFuncSetAttribute(gemm_h<1, DMODEL, H3, false>,
            cudaFuncAttributeMaxDynamicSharedMemorySize, GEMM_SMEM_BYTES);
        cudaFuncSetAttribute(attn_h<false>,
            cudaFuncAttributeMaxDynamicSharedMemorySize, ATTN_SMEM_BYTES);
        cudaFuncSetAttribute(attn_h<true>,
            cudaFuncAttributeMaxDynamicSharedMemorySize, ATTN_SMEM_BYTES);
        attr_done = true;
    }

    // 0) convert all inputs to fp16 (single launch)
    cvt_all<<<(N4_TOT + 255)/256, 256>>>(
        (const float4*)word_emb, (const float4*)emb_w,
        (const float4*)qkv_w0, (const float4*)qkv_w1,
        (uint2*)we_h, (uint2*)embw_h, (uint2*)w0_h, (uint2*)w1_h);

    // 1) h = transpose(word_emb) @ emb_w + emb_b
    gemm_h<0, DEMB, DMODEL, true><<<dim3(DMODEL/128, M_ROWS/128), 256,
        GEMM_SMEM_BYTES>>>(we_h, embw_h, emb_b, h_h);

    // 2) MHA #0
    gemm_h<1, DMODEL, H3, false><<<dim3(H3/128, M_ROWS/128), 256,
        GEMM_SMEM_BYTES>>>(h_h, w0_h, nullptr, heads_h);
    attn_h<false><<<dim3(64, 16), 256, ATTN_SMEM_BYTES>>>(
        heads_h, h_h, nullptr, nullptr);

    // 3) MHA #1 (keeps attn maps)
    gemm_h<1, DMODEL, H3, false><<<dim3(H3/128, M_ROWS/128), 256,
        GEMM_SMEM_BYTES>>>(h_h, w1_h, nullptr, heads_h);
    attn_h<true><<<dim3(64, 16), 256, ATTN_SMEM_BYTES>>>(
        heads_h, nullptr, core_out, P_h);

    // 4) attn_prob reformat [bn][i][j] -> [i][j][b][n]
    transpose_P<<<dim3(16, 1024), 256>>>(P_h, attn_out);
}